// round 7
// baseline (speedup 1.0000x reference)
#include <cuda_runtime.h>
#include <cuda_bf16.h>
#include <cstdint>
#include <math.h>

#define BB   2
#define SEQ  2048
#define DIM  1024
#define NH   16
#define HD   64
#define MT   (BB*SEQ)   // 4096

// Scratch (allocation-free rule: __device__ globals)
__device__ float g_q[BB*NH*SEQ*HD];
__device__ float g_k[BB*NH*SEQ*HD];
__device__ float g_v[BB*NH*SEQ*HD];
__device__ uint32_t g_xh[MT*DIM/2],    g_xl[MT*DIM/2];      // x split (bf16x2)
__device__ uint32_t g_wh[4*DIM*DIM/2], g_wl[4*DIM*DIM/2];   // wq|wk|wv|wo split
__device__ uint32_t g_ch[MT*DIM/2],    g_cl[MT*DIM/2];      // ctx split

// ---------------------------------------------------------------------------
// helpers
// ---------------------------------------------------------------------------
__device__ __forceinline__ uint32_t f2tf32(float x) {
    uint32_t r;
    asm("cvt.rna.tf32.f32 %0, %1;" : "=r"(r) : "f"(x));
    return r;
}
__device__ __forceinline__ uint32_t smem_u32(const void* p) {
    uint32_t a;
    asm("{ .reg .u64 t; cvta.to.shared.u64 t, %1; cvt.u32.u64 %0, t; }"
        : "=r"(a) : "l"(p));
    return a;
}
__device__ __forceinline__ void cp16(uint32_t dst, const void* src) {
    asm volatile("cp.async.ca.shared.global [%0], [%1], 16;" :: "r"(dst), "l"(src));
}
#define CP_COMMIT() asm volatile("cp.async.commit_group;" ::: "memory")
#define CP_WAIT0()  asm volatile("cp.async.wait_group 0;" ::: "memory")
#define CP_WAIT1()  asm volatile("cp.async.wait_group 1;" ::: "memory")

#define MMA_TF32(d, a, b) \
    asm volatile("mma.sync.aligned.m16n8k8.row.col.f32.tf32.tf32.f32 " \
        "{%0,%1,%2,%3}, {%4,%5,%6,%7}, {%8,%9}, {%0,%1,%2,%3};" \
        : "+f"((d)[0]), "+f"((d)[1]), "+f"((d)[2]), "+f"((d)[3]) \
        : "r"((a)[0]), "r"((a)[1]), "r"((a)[2]), "r"((a)[3]), \
          "r"((b)[0]), "r"((b)[1]))

#define MMA_BF16(d, a0, a1, a2, a3, b0, b1) \
    asm volatile("mma.sync.aligned.m16n8k16.row.col.f32.bf16.bf16.f32 " \
        "{%0,%1,%2,%3}, {%4,%5,%6,%7}, {%8,%9}, {%0,%1,%2,%3};" \
        : "+f"((d)[0]), "+f"((d)[1]), "+f"((d)[2]), "+f"((d)[3]) \
        : "r"(a0), "r"(a1), "r"(a2), "r"(a3), "r"(b0), "r"(b1))

#define LDSM4(d0, d1, d2, d3, a) \
    asm volatile("ldmatrix.sync.aligned.m8n8.x4.shared.b16 {%0,%1,%2,%3}, [%4];" \
        : "=r"(d0), "=r"(d1), "=r"(d2), "=r"(d3) : "r"(a))

// word = { low half = bf16(e0), high half = bf16(e1) }
__device__ __forceinline__ uint32_t packbf(float e0, float e1) {
    uint32_t r;
    asm("cvt.rn.bf16x2.f32 %0, %1, %2;" : "=r"(r) : "f"(e1), "f"(e0));
    return r;
}
__device__ __forceinline__ float ubf_lo(uint32_t w) { return __uint_as_float(w << 16); }
__device__ __forceinline__ float ubf_hi(uint32_t w) { return __uint_as_float(w & 0xFFFF0000u); }

// ===========================================================================
// split kernels: fp32 -> bf16 hi + bf16 lo (lo = rn(x - hi))
// ===========================================================================
__global__ __launch_bounds__(256)
void split_k(const float* __restrict__ src, uint32_t* __restrict__ hi,
             uint32_t* __restrict__ lo, int n8)
{
    int i = blockIdx.x * 256 + threadIdx.x;
    if (i >= n8) return;
    const float4* s = (const float4*)src;
    float4 a = s[2*i], b = s[2*i+1];
    uint32_t h0 = packbf(a.x, a.y), h1 = packbf(a.z, a.w);
    uint32_t h2 = packbf(b.x, b.y), h3 = packbf(b.z, b.w);
    ((uint4*)hi)[i] = make_uint4(h0, h1, h2, h3);
    ((uint4*)lo)[i] = make_uint4(
        packbf(a.x - ubf_lo(h0), a.y - ubf_hi(h0)),
        packbf(a.z - ubf_lo(h1), a.w - ubf_hi(h1)),
        packbf(b.x - ubf_lo(h2), b.y - ubf_hi(h2)),
        packbf(b.z - ubf_lo(h3), b.w - ubf_hi(h3)));
}

// all 4 weights in one launch: grid.y selects the weight
__global__ __launch_bounds__(256)
void split_w(const float* __restrict__ w0, const float* __restrict__ w1,
             const float* __restrict__ w2, const float* __restrict__ w3,
             uint32_t* __restrict__ hi, uint32_t* __restrict__ lo, int n8)
{
    int i = blockIdx.x * 256 + threadIdx.x;
    if (i >= n8) return;
    int y = blockIdx.y;
    const float* src = (y == 0) ? w0 : (y == 1) ? w1 : (y == 2) ? w2 : w3;
    hi += (size_t)y * (DIM*DIM/2);
    lo += (size_t)y * (DIM*DIM/2);
    const float4* s = (const float4*)src;
    float4 a = s[2*i], b = s[2*i+1];
    uint32_t h0 = packbf(a.x, a.y), h1 = packbf(a.z, a.w);
    uint32_t h2 = packbf(b.x, b.y), h3 = packbf(b.z, b.w);
    ((uint4*)hi)[i] = make_uint4(h0, h1, h2, h3);
    ((uint4*)lo)[i] = make_uint4(
        packbf(a.x - ubf_lo(h0), a.y - ubf_hi(h0)),
        packbf(a.z - ubf_lo(h1), a.w - ubf_hi(h1)),
        packbf(b.x - ubf_lo(h2), b.y - ubf_hi(h2)),
        packbf(b.z - ubf_lo(h3), b.w - ubf_hi(h3)));
}

// ===========================================================================
// 3xBF16 GEMM v2 (R6 core, occupancy 3): C = A @ W^T + bias
// ===========================================================================
#define GSTAGE2 32768
#define GEMM2_SMEM (2*GSTAGE2)   // 64 KB

template<bool SCATTER>
__global__ __launch_bounds__(128, 3)
void gemm_v2(const __nv_bfloat16* __restrict__ Ah, const __nv_bfloat16* __restrict__ Al,
             const __nv_bfloat16* __restrict__ Whb, const __nv_bfloat16* __restrict__ Wlb,
             const float* __restrict__ b0_, const float* __restrict__ b1_,
             const float* __restrict__ b2_,
             float* __restrict__ c0_, float* __restrict__ c1_, float* __restrict__ c2_)
{
    extern __shared__ char smem[];
    const uint32_t sb = smem_u32(smem);
    const int z = blockIdx.z;
    const __nv_bfloat16* Wh = Whb + (size_t)z * (DIM*DIM);
    const __nv_bfloat16* Wl = Wlb + (size_t)z * (DIM*DIM);
    const float* bias = (z == 0) ? b0_ : (z == 1) ? b1_ : b2_;
    float* C          = (z == 0) ? c0_ : (z == 1) ? c1_ : c2_;

    const int tid = threadIdx.x, lane = tid & 31, wid = tid >> 5;
    const int g = lane >> 2, tig = lane & 3;
    const int wm = wid & 1, wn = wid >> 1;
    const int m0 = blockIdx.y * 128, n0 = blockIdx.x * 128;

    const char* gsrc[4];
    gsrc[0] = (const char*)(Ah + (size_t)m0 * DIM);
    gsrc[1] = (const char*)(Al + (size_t)m0 * DIM);
    gsrc[2] = (const char*)(Wh + (size_t)n0 * DIM);
    gsrc[3] = (const char*)(Wl + (size_t)n0 * DIM);
    uint32_t sOff[4], gOff[4];
#pragma unroll
    for (int rep = 0; rep < 4; rep++) {
        int id = tid + 128*rep;
        int row = id >> 2, cc = id & 3;
        sOff[rep] = (uint32_t)((row >> 1)*128 + ((((row & 1)*4 + cc) ^ ((row >> 1) & 7)) * 16));
        gOff[rep] = (uint32_t)((row * DIM + cc*8) * 2);
    }

    const int rl  = ((lane >> 3) & 1) * 8 + (lane & 7);
    const int chl = lane >> 4;
    uint32_t aoff[2];
#pragma unroll
    for (int kk = 0; kk < 2; kk++)
        aoff[kk] = (uint32_t)((rl >> 1)*128 + ((((rl & 1)*4 + 2*kk + chl) ^ ((rl >> 1) & 7)) * 16));

    float acc[4][8][4];
#pragma unroll
    for (int i = 0; i < 4; i++)
#pragma unroll
        for (int j = 0; j < 8; j++)
#pragma unroll
            for (int q = 0; q < 4; q++) acc[i][j][q] = 0.f;

    auto issue = [&](int chunk) {
        uint32_t st = sb + (uint32_t)(chunk & 1) * GSTAGE2;
        uint32_t kb = (uint32_t)(chunk * 32 * 2);
#pragma unroll
        for (int rep = 0; rep < 4; rep++)
#pragma unroll
            for (int comp = 0; comp < 4; comp++)
                cp16(st + comp*8192u + sOff[rep], gsrc[comp] + gOff[rep] + kb);
        CP_COMMIT();
    };

    issue(0);
    for (int c = 0; c < DIM/32; ++c) {
        if (c < DIM/32 - 1) { issue(c + 1); CP_WAIT1(); }
        else                { CP_WAIT0(); }
        __syncthreads();

        const uint32_t stage = sb + (uint32_t)(c & 1) * GSTAGE2;
#pragma unroll
        for (int kk = 0; kk < 2; kk++) {
            uint32_t ah[4][4], al[4][4];
#pragma unroll
            for (int i = 0; i < 4; i++) {
                uint32_t base = stage + (uint32_t)(wm*4096 + i*1024) + aoff[kk];
                LDSM4(ah[i][0], ah[i][1], ah[i][2], ah[i][3], base);
                LDSM4(al[i][0], al[i][1], al[i][2], al[i][3], base + 8192u);
            }
#pragma unroll
            for (int nn = 0; nn < 4; nn++) {
                uint32_t base = stage + 16384u + (uint32_t)(wn*4096 + nn*1024) + aoff[kk];
                uint32_t q0, q1, q2, q3, r0_, r1_, r2_, r3_;
                LDSM4(q0, q1, q2, q3, base);
                LDSM4(r0_, r1_, r2_, r3_, base + 8192u);
                const int j0 = nn*2, j1 = nn*2 + 1;
#pragma unroll
                for (int i = 0; i < 4; i++) {
                    MMA_BF16(acc[i][j0], ah[i][0], ah[i][1], ah[i][2], ah[i][3], q0, q2);
                    MMA_BF16(acc[i][j0], ah[i][0], ah[i][1], ah[i][2], ah[i][3], r0_, r2_);
                    MMA_BF16(acc[i][j0], al[i][0], al[i][1], al[i][2], al[i][3], q0, q2);
                    MMA_BF16(acc[i][j1], ah[i][0], ah[i][1], ah[i][2], ah[i][3], q1, q3);
                    MMA_BF16(acc[i][j1], ah[i][0], ah[i][1], ah[i][2], ah[i][3], r1_, r3_);
                    MMA_BF16(acc[i][j1], al[i][0], al[i][1], al[i][2], al[i][3], q1, q3);
                }
            }
        }
        __syncthreads();
    }

#pragma unroll
    for (int i = 0; i < 4; i++) {
        int r = m0 + wm*64 + i*16 + g;
#pragma unroll
        for (int j = 0; j < 8; j++) {
            int n = n0 + wn*64 + j*8 + 2*tig;
            float b0 = __ldg(bias + n), b1 = __ldg(bias + n + 1);
#pragma unroll
            for (int half = 0; half < 2; half++) {
                int m = r + half*8;
                float v0 = acc[i][j][half*2] + b0;
                float v1 = acc[i][j][half*2+1] + b1;
                if (SCATTER) {
                    float2 o = make_float2(__uint_as_float(f2tf32(v0)),
                                           __uint_as_float(f2tf32(v1)));
                    int b_ = m >> 11, s_ = m & (SEQ - 1);
                    int head = n >> 6, hd = n & 63;
                    *(float2*)&C[(((size_t)(b_*NH + head)) * SEQ + s_) * HD + hd] = o;
                } else {
                    *(float2*)&C[(size_t)m * DIM + n] = make_float2(v0, v1);
                }
            }
        }
    }
}

// ===========================================================================
// Tensor-core flash attention v2: Q tile 128 (2 strips/warp), K/V fragments
// loaded once and reused across strips. grid=(S/128, H, B), 128 threads.
// Smem: 2 KV stages (K 64x68, V 64x72) + P/Q buffer 128x68.
// ===========================================================================
#define ATTN_STAGE_F  (68*64 + 72*64)                 // 8960 floats
#define ATTN_P_F      (128*68)                        // 8704 floats
#define ATTN_SMEM     ((2*ATTN_STAGE_F + ATTN_P_F) * 4)   // 106496 bytes

__global__ __launch_bounds__(128, 2)
void attn_mma(const float* __restrict__ q, const float* __restrict__ k,
              const float* __restrict__ v,
              uint32_t* __restrict__ ch, uint32_t* __restrict__ cl)
{
    extern __shared__ float sm[];
    const uint32_t sb = smem_u32(sm);
    const int tid = threadIdx.x;
    const int lane = tid & 31, wm = tid >> 5;
    const int g = lane >> 2, tig = lane & 3;
    const int b = blockIdx.z, h = blockIdx.y, q0 = blockIdx.x * 128;

    const float* qg = q + (((size_t)(b*NH + h)) * SEQ + q0) * HD;
    const float* kg = k + ((size_t)(b*NH + h)) * SEQ * HD;
    const float* vg = v + ((size_t)(b*NH + h)) * SEQ * HD;

    float* Pbuf = sm + 2*ATTN_STAGE_F;

    // ---- stage Q (128 rows, x 1/8 exact) into Pbuf, then capture frags ----
#pragma unroll
    for (int j = 0; j < 16; j++) {
        int id = tid + 128*j;                  // 0..2047
        int r = id >> 4, c = (id & 15) * 4;
        float4 t = *(const float4*)(qg + r*HD + c);
        t.x *= 0.125f; t.y *= 0.125f; t.z *= 0.125f; t.w *= 0.125f;
        *(float4*)&Pbuf[r*68 + c] = t;
    }
    __syncthreads();
    uint32_t qf[2][8][4];
#pragma unroll
    for (int st = 0; st < 2; st++) {
        int r0 = wm*32 + st*16 + g;
#pragma unroll
        for (int kc = 0; kc < 8; kc++) {
            qf[st][kc][0] = __float_as_uint(Pbuf[ r0      *68 + kc*8 + tig    ]);
            qf[st][kc][1] = __float_as_uint(Pbuf[(r0 + 8) *68 + kc*8 + tig    ]);
            qf[st][kc][2] = __float_as_uint(Pbuf[ r0      *68 + kc*8 + tig + 4]);
            qf[st][kc][3] = __float_as_uint(Pbuf[(r0 + 8) *68 + kc*8 + tig + 4]);
        }
    }

    // ---- preload KV tile 0 ----
#pragma unroll
    for (int j = 0; j < 8; j++) {
        int id = tid + 128*j;
        int r = id >> 4, c = (id & 15) * 4;
        cp16(sb + (r*68 + c)*4,        kg + r*HD + c);
        cp16(sb + (4352 + r*72 + c)*4, vg + r*HD + c);
    }
    CP_COMMIT();

    float o[2][8][4];
#pragma unroll
    for (int st = 0; st < 2; st++)
#pragma unroll
        for (int nc = 0; nc < 8; nc++)
#pragma unroll
            for (int e = 0; e < 4; e++) o[st][nc][e] = 0.f;
    float mM[2][2], lL[2][2];
#pragma unroll
    for (int st = 0; st < 2; st++) { mM[st][0] = mM[st][1] = -1e30f;
                                     lL[st][0] = lL[st][1] = 0.f; }

    for (int t = 0; t < SEQ/64; ++t) {
        CP_WAIT0();
        __syncthreads();
        if (t < SEQ/64 - 1) {
            int stg = ((t+1) & 1) * ATTN_STAGE_F;
            const float* kn = kg + (size_t)(t+1)*64*HD;
            const float* vn = vg + (size_t)(t+1)*64*HD;
#pragma unroll
            for (int j = 0; j < 8; j++) {
                int id = tid + 128*j;
                int r = id >> 4, c = (id & 15) * 4;
                cp16(sb + (stg + r*68 + c)*4,        kn + r*HD + c);
                cp16(sb + (stg + 4352 + r*72 + c)*4, vn + r*HD + c);
            }
            CP_COMMIT();
        }
        const float* Ks = sm + (t & 1) * ATTN_STAGE_F;
        const float* Vs = Ks + 4352;

        // ---- S = (Q/8) K^T : K frags shared across both strips ----
        float s[2][8][4];
#pragma unroll
        for (int nc = 0; nc < 8; nc++) {
#pragma unroll
            for (int e = 0; e < 4; e++) { s[0][nc][e] = 0.f; s[1][nc][e] = 0.f; }
#pragma unroll
            for (int kc = 0; kc < 8; kc++) {
                uint32_t bfr[2];
                bfr[0] = __float_as_uint(Ks[(nc*8 + g)*68 + kc*8 + tig    ]);
                bfr[1] = __float_as_uint(Ks[(nc*8 + g)*68 + kc*8 + tig + 4]);
                MMA_TF32(s[0][nc], qf[0][kc], bfr);
                MMA_TF32(s[1][nc], qf[1][kc], bfr);
            }
        }

        // ---- online softmax per strip ----
#pragma unroll
        for (int st = 0; st < 2; st++) {
            float mx0 = -1e30f, mx1 = -1e30f;
#pragma unroll
            for (int nc = 0; nc < 8; nc++) {
                mx0 = fmaxf(mx0, fmaxf(s[st][nc][0], s[st][nc][1]));
                mx1 = fmaxf(mx1, fmaxf(s[st][nc][2], s[st][nc][3]));
            }
            mx0 = fmaxf(mx0, __shfl_xor_sync(0xffffffffu, mx0, 1));
            mx0 = fmaxf(mx0, __shfl_xor_sync(0xffffffffu, mx0, 2));
            mx1 = fmaxf(mx1, __shfl_xor_sync(0xffffffffu, mx1, 1));
            mx1 = fmaxf(mx1, __shfl_xor_sync(0xffffffffu, mx1, 2));
            float mn0 = fmaxf(mM[st][0], mx0), mn1 = fmaxf(mM[st][1], mx1);
            float c0 = __expf(mM[st][0] - mn0), c1 = __expf(mM[st][1] - mn1);
            float sum0 = 0.f, sum1 = 0.f;
#pragma unroll
            for (int nc = 0; nc < 8; nc++) {
                s[st][nc][0] = __expf(s[st][nc][0] - mn0); sum0 += s[st][nc][0];
                s[st][nc][1] = __expf(s[st][nc][1] - mn0); sum0 += s[st][nc][1];
                s[st][nc][2] = __expf(s[st][nc][2] - mn1); sum1 += s[st][nc][2];
                s[st][nc][3] = __expf(s[st][nc][3] - mn1); sum1 += s[st][nc][3];
            }
            sum0 += __shfl_xor_sync(0xffffffffu, sum0, 1);
            sum0 += __shfl_xor_sync(0xffffffffu, sum0, 2);
            sum1 += __shfl_xor_sync(0xffffffffu, sum1, 1);
            sum1 += __shfl_xor_sync(0xffffffffu, sum1, 2);
            lL[st][0] = lL[st][0]*c0 + sum0;  lL[st][1] = lL[st][1]*c1 + sum1;
            mM[st][0] = mn0;                  mM[st][1] = mn1;
#pragma unroll
            for (int nc = 0; nc < 8; nc++) {
                o[st][nc][0] *= c0; o[st][nc][1] *= c0;
                o[st][nc][2] *= c1; o[st][nc][3] *= c1;
            }
            // P (tf32-rounded) -> smem, warp-private rows
            int r0 = wm*32 + st*16 + g;
#pragma unroll
            for (int nc = 0; nc < 8; nc++) {
                *(float2*)&Pbuf[ r0    *68 + nc*8 + 2*tig] =
                    make_float2(__uint_as_float(f2tf32(s[st][nc][0])),
                                __uint_as_float(f2tf32(s[st][nc][1])));
                *(float2*)&Pbuf[(r0+8) *68 + nc*8 + 2*tig] =
                    make_float2(__uint_as_float(f2tf32(s[st][nc][2])),
                                __uint_as_float(f2tf32(s[st][nc][3])));
            }
        }
        __syncwarp();

        // ---- O += P V : V frags shared across both strips ----
#pragma unroll
        for (int kc = 0; kc < 8; kc++) {
            uint32_t a0[4], a1[4];
            int ra = wm*32 + g;
            a0[0] = __float_as_uint(Pbuf[ ra      *68 + kc*8 + tig    ]);
            a0[1] = __float_as_uint(Pbuf[(ra + 8) *68 + kc*8 + tig    ]);
            a0[2] = __float_as_uint(Pbuf[ ra      *68 + kc*8 + tig + 4]);
            a0[3] = __float_as_uint(Pbuf[(ra + 8) *68 + kc*8 + tig + 4]);
            a1[0] = __float_as_uint(Pbuf[(ra + 16)*68 + kc*8 + tig    ]);
            a1[1] = __float_as_uint(Pbuf[(ra + 24)*68 + kc*8 + tig    ]);
            a1[2] = __float_as_uint(Pbuf[(ra + 16)*68 + kc*8 + tig + 4]);
            a1[3] = __float_as_uint(Pbuf[(ra + 24)*68 + kc*8 + tig + 4]);
#pragma unroll
            for (int nc = 0; nc < 8; nc++) {
                uint32_t bfr[2];
                bfr[0] = __float_as_uint(Vs[(kc*8 + tig    )*72 + nc*8 + g]);
                bfr[1] = __float_as_uint(Vs[(kc*8 + tig + 4)*72 + nc*8 + g]);
                MMA_TF32(o[0][nc], a0, bfr);
                MMA_TF32(o[1][nc], a1, bfr);
            }
        }
        __syncwarp();
    }

    // ---- epilogue: write ctx as bf16 hi/lo pairs ----
#pragma unroll
    for (int st = 0; st < 2; st++) {
        float inv0 = 1.f / lL[st][0], inv1 = 1.f / lL[st][1];
        int r0 = wm*32 + st*16 + g;
        size_t base0 = ((size_t)(b*SEQ + q0 + r0    )) * DIM + h*HD;
        size_t base1 = ((size_t)(b*SEQ + q0 + r0 + 8)) * DIM + h*HD;
#pragma unroll
        for (int nc = 0; nc < 8; nc++) {
            float v0 = o[st][nc][0]*inv0, v1 = o[st][nc][1]*inv0;
            uint32_t hw = packbf(v0, v1);
            uint32_t lw = packbf(v0 - ubf_lo(hw), v1 - ubf_hi(hw));
            size_t idx = (base0 + nc*8 + 2*tig) >> 1;
            ch[idx] = hw; cl[idx] = lw;
            v0 = o[st][nc][2]*inv1; v1 = o[st][nc][3]*inv1;
            hw = packbf(v0, v1);
            lw = packbf(v0 - ubf_lo(hw), v1 - ubf_hi(hw));
            idx = (base1 + nc*8 + 2*tig) >> 1;
            ch[idx] = hw; cl[idx] = lw;
        }
    }
}

// ===========================================================================
extern "C" void kernel_launch(void* const* d_in, const int* in_sizes, int n_in,
                              void* d_out, int out_size)
{
    const float* x  = (const float*)d_in[0];
    const float* wq = (const float*)d_in[1];
    const float* bq = (const float*)d_in[2];
    const float* wk = (const float*)d_in[3];
    const float* bk = (const float*)d_in[4];
    const float* wv = (const float*)d_in[5];
    const float* bv = (const float*)d_in[6];
    const float* wo = (const float*)d_in[7];
    const float* bo = (const float*)d_in[8];

    float *qp, *kp, *vp;
    uint32_t *xh, *xl, *wh, *wl, *ch, *cl;
    cudaGetSymbolAddress((void**)&qp, g_q);
    cudaGetSymbolAddress((void**)&kp, g_k);
    cudaGetSymbolAddress((void**)&vp, g_v);
    cudaGetSymbolAddress((void**)&xh, g_xh);
    cudaGetSymbolAddress((void**)&xl, g_xl);
    cudaGetSymbolAddress((void**)&wh, g_wh);
    cudaGetSymbolAddress((void**)&wl, g_wl);
    cudaGetSymbolAddress((void**)&ch, g_ch);
    cudaGetSymbolAddress((void**)&cl, g_cl);

    cudaFuncSetAttribute(attn_mma,
                         cudaFuncAttributeMaxDynamicSharedMemorySize, ATTN_SMEM);
    cudaFuncSetAttribute(gemm_v2<true>,
                         cudaFuncAttributeMaxDynamicSharedMemorySize, GEMM2_SMEM);
    cudaFuncSetAttribute(gemm_v2<false>,
                         cudaFuncAttributeMaxDynamicSharedMemorySize, GEMM2_SMEM);

    const int WE = DIM*DIM;
    // 1) split x (1 launch) + all weights (1 launch, grid.y = 4)
    split_k<<<MT*DIM/8/256, 256>>>(x, xh, xl, MT*DIM/8);
    split_w<<<dim3(WE/8/256, 4), 256>>>(wq, wk, wv, wo, wh, wl, WE/8);

    const __nv_bfloat16* xh_b = (const __nv_bfloat16*)xh;
    const __nv_bfloat16* xl_b = (const __nv_bfloat16*)xl;
    const __nv_bfloat16* wh_b = (const __nv_bfloat16*)wh;
    const __nv_bfloat16* wl_b = (const __nv_bfloat16*)wl;
    const __nv_bfloat16* ch_b = (const __nv_bfloat16*)ch;
    const __nv_bfloat16* cl_b = (const __nv_bfloat16*)cl;
    float* out = (float*)d_out;

    // 2) fused QKV projections
    gemm_v2<true><<<dim3(DIM/128, MT/128, 3), 128, GEMM2_SMEM>>>(
        xh_b, xl_b, wh_b, wl_b, bq, bk, bv, qp, kp, vp);
    // 3) attention (Q tile 128; writes ctx hi/lo)
    attn_mma<<<dim3(SEQ/128, NH, BB), 128, ATTN_SMEM>>>(qp, kp, vp, ch, cl);
    // 4) output projection
    gemm_v2<false><<<dim3(DIM/128, MT/128, 1), 128, GEMM2_SMEM>>>(
        ch_b, cl_b, wh_b + (size_t)3*WE, wl_b + (size_t)3*WE,
        bo, bo, bo, out, out, out);
}

// round 8
// speedup vs baseline: 1.0569x; 1.0569x over previous
#include <cuda_runtime.h>
#include <cuda_bf16.h>
#include <cstdint>
#include <math.h>

#define BB   2
#define SEQ  2048
#define DIM  1024
#define NH   16
#define HD   64
#define MT   (BB*SEQ)   // 4096

// Scratch (allocation-free rule: __device__ globals)
__device__ float g_q[BB*NH*SEQ*HD];
__device__ float g_k[BB*NH*SEQ*HD];
__device__ float g_v[BB*NH*SEQ*HD];
__device__ uint32_t g_xh[MT*DIM/2],    g_xl[MT*DIM/2];
__device__ uint32_t g_wh[4*DIM*DIM/2], g_wl[4*DIM*DIM/2];
__device__ uint32_t g_ch[MT*DIM/2],    g_cl[MT*DIM/2];

// ---------------------------------------------------------------------------
// helpers
// ---------------------------------------------------------------------------
__device__ __forceinline__ uint32_t f2tf32(float x) {
    uint32_t r;
    asm("cvt.rna.tf32.f32 %0, %1;" : "=r"(r) : "f"(x));
    return r;
}
__device__ __forceinline__ uint32_t smem_u32(const void* p) {
    uint32_t a;
    asm("{ .reg .u64 t; cvta.to.shared.u64 t, %1; cvt.u32.u64 %0, t; }"
        : "=r"(a) : "l"(p));
    return a;
}
__device__ __forceinline__ void cp16(uint32_t dst, const void* src) {
    asm volatile("cp.async.ca.shared.global [%0], [%1], 16;" :: "r"(dst), "l"(src));
}
#define CP_COMMIT() asm volatile("cp.async.commit_group;" ::: "memory")
#define CP_WAIT0()  asm volatile("cp.async.wait_group 0;" ::: "memory")
#define CP_WAIT1()  asm volatile("cp.async.wait_group 1;" ::: "memory")

#define MMA_TF32(d, a, b) \
    asm volatile("mma.sync.aligned.m16n8k8.row.col.f32.tf32.tf32.f32 " \
        "{%0,%1,%2,%3}, {%4,%5,%6,%7}, {%8,%9}, {%0,%1,%2,%3};" \
        : "+f"((d)[0]), "+f"((d)[1]), "+f"((d)[2]), "+f"((d)[3]) \
        : "r"((a)[0]), "r"((a)[1]), "r"((a)[2]), "r"((a)[3]), \
          "r"((b)[0]), "r"((b)[1]))

#define MMA_BF16(d, a0, a1, a2, a3, b0, b1) \
    asm volatile("mma.sync.aligned.m16n8k16.row.col.f32.bf16.bf16.f32 " \
        "{%0,%1,%2,%3}, {%4,%5,%6,%7}, {%8,%9}, {%0,%1,%2,%3};" \
        : "+f"((d)[0]), "+f"((d)[1]), "+f"((d)[2]), "+f"((d)[3]) \
        : "r"(a0), "r"(a1), "r"(a2), "r"(a3), "r"(b0), "r"(b1))

#define LDSM4(d0, d1, d2, d3, a) \
    asm volatile("ldmatrix.sync.aligned.m8n8.x4.shared.b16 {%0,%1,%2,%3}, [%4];" \
        : "=r"(d0), "=r"(d1), "=r"(d2), "=r"(d3) : "r"(a))

__device__ __forceinline__ uint32_t packbf(float e0, float e1) {
    uint32_t r;
    asm("cvt.rn.bf16x2.f32 %0, %1, %2;" : "=r"(r) : "f"(e1), "f"(e0));
    return r;
}
__device__ __forceinline__ float ubf_lo(uint32_t w) { return __uint_as_float(w << 16); }
__device__ __forceinline__ float ubf_hi(uint32_t w) { return __uint_as_float(w & 0xFFFF0000u); }

// ===========================================================================
// split kernels: fp32 -> bf16 hi + bf16 lo
// ===========================================================================
__global__ __launch_bounds__(256)
void split_k(const float* __restrict__ src, uint32_t* __restrict__ hi,
             uint32_t* __restrict__ lo, int n8)
{
    int i = blockIdx.x * 256 + threadIdx.x;
    if (i >= n8) return;
    const float4* s = (const float4*)src;
    float4 a = s[2*i], b = s[2*i+1];
    uint32_t h0 = packbf(a.x, a.y), h1 = packbf(a.z, a.w);
    uint32_t h2 = packbf(b.x, b.y), h3 = packbf(b.z, b.w);
    ((uint4*)hi)[i] = make_uint4(h0, h1, h2, h3);
    ((uint4*)lo)[i] = make_uint4(
        packbf(a.x - ubf_lo(h0), a.y - ubf_hi(h0)),
        packbf(a.z - ubf_lo(h1), a.w - ubf_hi(h1)),
        packbf(b.x - ubf_lo(h2), b.y - ubf_hi(h2)),
        packbf(b.z - ubf_lo(h3), b.w - ubf_hi(h3)));
}

__global__ __launch_bounds__(256)
void split_w(const float* __restrict__ w0, const float* __restrict__ w1,
             const float* __restrict__ w2, const float* __restrict__ w3,
             uint32_t* __restrict__ hi, uint32_t* __restrict__ lo, int n8)
{
    int i = blockIdx.x * 256 + threadIdx.x;
    if (i >= n8) return;
    int y = blockIdx.y;
    const float* src = (y == 0) ? w0 : (y == 1) ? w1 : (y == 2) ? w2 : w3;
    hi += (size_t)y * (DIM*DIM/2);
    lo += (size_t)y * (DIM*DIM/2);
    const float4* s = (const float4*)src;
    float4 a = s[2*i], b = s[2*i+1];
    uint32_t h0 = packbf(a.x, a.y), h1 = packbf(a.z, a.w);
    uint32_t h2 = packbf(b.x, b.y), h3 = packbf(b.z, b.w);
    ((uint4*)hi)[i] = make_uint4(h0, h1, h2, h3);
    ((uint4*)lo)[i] = make_uint4(
        packbf(a.x - ubf_lo(h0), a.y - ubf_hi(h0)),
        packbf(a.z - ubf_lo(h1), a.w - ubf_hi(h1)),
        packbf(b.x - ubf_lo(h2), b.y - ubf_hi(h2)),
        packbf(b.z - ubf_lo(h3), b.w - ubf_hi(h3)));
}

// ===========================================================================
// 3xBF16 GEMM v2 — exact R6 configuration (occupancy 2, proven)
// ===========================================================================
#define GSTAGE2 32768
#define GEMM2_SMEM (2*GSTAGE2)   // 64 KB

template<bool SCATTER>
__global__ __launch_bounds__(128, 2)
void gemm_v2(const __nv_bfloat16* __restrict__ Ah, const __nv_bfloat16* __restrict__ Al,
             const __nv_bfloat16* __restrict__ Whb, const __nv_bfloat16* __restrict__ Wlb,
             const float* __restrict__ b0_, const float* __restrict__ b1_,
             const float* __restrict__ b2_,
             float* __restrict__ c0_, float* __restrict__ c1_, float* __restrict__ c2_)
{
    extern __shared__ char smem[];
    const uint32_t sb = smem_u32(smem);
    const int z = blockIdx.z;
    const __nv_bfloat16* Wh = Whb + (size_t)z * (DIM*DIM);
    const __nv_bfloat16* Wl = Wlb + (size_t)z * (DIM*DIM);
    const float* bias = (z == 0) ? b0_ : (z == 1) ? b1_ : b2_;
    float* C          = (z == 0) ? c0_ : (z == 1) ? c1_ : c2_;

    const int tid = threadIdx.x, lane = tid & 31, wid = tid >> 5;
    const int g = lane >> 2, tig = lane & 3;
    const int wm = wid & 1, wn = wid >> 1;
    const int m0 = blockIdx.y * 128, n0 = blockIdx.x * 128;

    const char* gsrc[4];
    gsrc[0] = (const char*)(Ah + (size_t)m0 * DIM);
    gsrc[1] = (const char*)(Al + (size_t)m0 * DIM);
    gsrc[2] = (const char*)(Wh + (size_t)n0 * DIM);
    gsrc[3] = (const char*)(Wl + (size_t)n0 * DIM);
    uint32_t sOff[4], gOff[4];
#pragma unroll
    for (int rep = 0; rep < 4; rep++) {
        int id = tid + 128*rep;
        int row = id >> 2, cc = id & 3;
        sOff[rep] = (uint32_t)((row >> 1)*128 + ((((row & 1)*4 + cc) ^ ((row >> 1) & 7)) * 16));
        gOff[rep] = (uint32_t)((row * DIM + cc*8) * 2);
    }

    const int rl  = ((lane >> 3) & 1) * 8 + (lane & 7);
    const int chl = lane >> 4;
    uint32_t aoff[2];
#pragma unroll
    for (int kk = 0; kk < 2; kk++)
        aoff[kk] = (uint32_t)((rl >> 1)*128 + ((((rl & 1)*4 + 2*kk + chl) ^ ((rl >> 1) & 7)) * 16));

    float acc[4][8][4];
#pragma unroll
    for (int i = 0; i < 4; i++)
#pragma unroll
        for (int j = 0; j < 8; j++)
#pragma unroll
            for (int q = 0; q < 4; q++) acc[i][j][q] = 0.f;

    auto issue = [&](int chunk) {
        uint32_t st = sb + (uint32_t)(chunk & 1) * GSTAGE2;
        uint32_t kb = (uint32_t)(chunk * 32 * 2);
#pragma unroll
        for (int rep = 0; rep < 4; rep++)
#pragma unroll
            for (int comp = 0; comp < 4; comp++)
                cp16(st + comp*8192u + sOff[rep], gsrc[comp] + gOff[rep] + kb);
        CP_COMMIT();
    };

    issue(0);
    for (int c = 0; c < DIM/32; ++c) {
        if (c < DIM/32 - 1) { issue(c + 1); CP_WAIT1(); }
        else                { CP_WAIT0(); }
        __syncthreads();

        const uint32_t stage = sb + (uint32_t)(c & 1) * GSTAGE2;
#pragma unroll
        for (int kk = 0; kk < 2; kk++) {
            uint32_t ah[4][4], al[4][4];
#pragma unroll
            for (int i = 0; i < 4; i++) {
                uint32_t base = stage + (uint32_t)(wm*4096 + i*1024) + aoff[kk];
                LDSM4(ah[i][0], ah[i][1], ah[i][2], ah[i][3], base);
                LDSM4(al[i][0], al[i][1], al[i][2], al[i][3], base + 8192u);
            }
#pragma unroll
            for (int nn = 0; nn < 4; nn++) {
                uint32_t base = stage + 16384u + (uint32_t)(wn*4096 + nn*1024) + aoff[kk];
                uint32_t q0, q1, q2, q3, r0_, r1_, r2_, r3_;
                LDSM4(q0, q1, q2, q3, base);
                LDSM4(r0_, r1_, r2_, r3_, base + 8192u);
                const int j0 = nn*2, j1 = nn*2 + 1;
#pragma unroll
                for (int i = 0; i < 4; i++) {
                    MMA_BF16(acc[i][j0], ah[i][0], ah[i][1], ah[i][2], ah[i][3], q0, q2);
                    MMA_BF16(acc[i][j0], ah[i][0], ah[i][1], ah[i][2], ah[i][3], r0_, r2_);
                    MMA_BF16(acc[i][j0], al[i][0], al[i][1], al[i][2], al[i][3], q0, q2);
                    MMA_BF16(acc[i][j1], ah[i][0], ah[i][1], ah[i][2], ah[i][3], q1, q3);
                    MMA_BF16(acc[i][j1], ah[i][0], ah[i][1], ah[i][2], ah[i][3], r1_, r3_);
                    MMA_BF16(acc[i][j1], al[i][0], al[i][1], al[i][2], al[i][3], q1, q3);
                }
            }
        }
        __syncthreads();
    }

#pragma unroll
    for (int i = 0; i < 4; i++) {
        int r = m0 + wm*64 + i*16 + g;
#pragma unroll
        for (int j = 0; j < 8; j++) {
            int n = n0 + wn*64 + j*8 + 2*tig;
            float b0 = __ldg(bias + n), b1 = __ldg(bias + n + 1);
#pragma unroll
            for (int half = 0; half < 2; half++) {
                int m = r + half*8;
                float v0 = acc[i][j][half*2] + b0;
                float v1 = acc[i][j][half*2+1] + b1;
                if (SCATTER) {
                    float2 o = make_float2(__uint_as_float(f2tf32(v0)),
                                           __uint_as_float(f2tf32(v1)));
                    int b_ = m >> 11, s_ = m & (SEQ - 1);
                    int head = n >> 6, hd = n & 63;
                    *(float2*)&C[(((size_t)(b_*NH + head)) * SEQ + s_) * HD + hd] = o;
                } else {
                    *(float2*)&C[(size_t)m * DIM + n] = make_float2(v0, v1);
                }
            }
        }
    }
}

// ===========================================================================
// Tensor-core flash attention (tf32), R6 64-row tile + ldmatrix fragment
// loads for K (B-frag) and P (A-frag). V stays scalar (proven path).
// grid=(S/64, H, B), 128 threads, occ 2.
// ===========================================================================
#define ATTN_STAGE_F  (68*64 + 72*64)                  // 8960 floats
#define ATTN_SMEM     ((2*ATTN_STAGE_F + 68*64) * 4)   // 89088 bytes

__global__ __launch_bounds__(128, 2)
void attn_mma(const float* __restrict__ q, const float* __restrict__ k,
              const float* __restrict__ v,
              uint32_t* __restrict__ ch, uint32_t* __restrict__ cl)
{
    extern __shared__ float sm[];
    const uint32_t sb = smem_u32(sm);
    const int tid = threadIdx.x;
    const int lane = tid & 31, wm = tid >> 5;
    const int g = lane >> 2, tig = lane & 3;
    const int b = blockIdx.z, h = blockIdx.y, q0 = blockIdx.x * 64;

    const float* qg = q + (((size_t)(b*NH + h)) * SEQ + q0) * HD;
    const float* kg = k + ((size_t)(b*NH + h)) * SEQ * HD;
    const float* vg = v + ((size_t)(b*NH + h)) * SEQ * HD;

    float* Pbuf = sm + 2*ATTN_STAGE_F;
    const uint32_t pbufAddr = sb + 2*ATTN_STAGE_F*4;

    // ldmatrix lane-address components
    const int r8 = lane & 7, grp = lane >> 3;
    // K B-frag: tiles = [rows nc*8..+7] x [cols {0,4,8,12}+p*16] (stride 68)
    const uint32_t laneK = (uint32_t)((r8*68 + grp*4) * 4);
    // P A-frag: tiles = [rows wm*16 + (grp&1)*8 + r] x [cols (grp>>1)*4] (stride 68)
    const uint32_t laneP = (uint32_t)(((wm*16 + ((grp & 1) << 3) + r8)*68 + (grp >> 1)*4) * 4);

    // ---- stage Q (x 1/8, exact) then capture A-fragments ----
#pragma unroll
    for (int j = 0; j < 8; j++) {
        int id = tid + 128*j;
        int r = id >> 4, c = (id & 15) * 4;
        float4 t = *(const float4*)(qg + r*HD + c);
        t.x *= 0.125f; t.y *= 0.125f; t.z *= 0.125f; t.w *= 0.125f;
        *(float4*)&Pbuf[r*68 + c] = t;
    }
    __syncthreads();
    uint32_t qf[8][4];
#pragma unroll
    for (int kc = 0; kc < 8; kc++)
        LDSM4(qf[kc][0], qf[kc][1], qf[kc][2], qf[kc][3], pbufAddr + kc*32 + laneP);

    // ---- preload KV tile 0 ----
#pragma unroll
    for (int j = 0; j < 8; j++) {
        int id = tid + 128*j;
        int r = id >> 4, c = (id & 15) * 4;
        cp16(sb + (r*68 + c)*4,        kg + r*HD + c);
        cp16(sb + (4352 + r*72 + c)*4, vg + r*HD + c);
    }
    CP_COMMIT();

    float o[8][4];
#pragma unroll
    for (int nc = 0; nc < 8; nc++)
#pragma unroll
        for (int e = 0; e < 4; e++) o[nc][e] = 0.f;
    float m0 = -1e30f, m1 = -1e30f, l0 = 0.f, l1 = 0.f;
    const int r0 = wm*16 + g;

    for (int t = 0; t < SEQ/64; ++t) {
        CP_WAIT0();
        __syncthreads();
        if (t < SEQ/64 - 1) {
            int st = ((t+1) & 1) * ATTN_STAGE_F;
            const float* kn = kg + (size_t)(t+1)*64*HD;
            const float* vn = vg + (size_t)(t+1)*64*HD;
#pragma unroll
            for (int j = 0; j < 8; j++) {
                int id = tid + 128*j;
                int r = id >> 4, c = (id & 15) * 4;
                cp16(sb + (st + r*68 + c)*4,        kn + r*HD + c);
                cp16(sb + (st + 4352 + r*72 + c)*4, vn + r*HD + c);
            }
            CP_COMMIT();
        }
        const uint32_t kstAddr = sb + (uint32_t)(t & 1) * (ATTN_STAGE_F*4);
        const float* Vs = sm + (t & 1) * ATTN_STAGE_F + 4352;

        // ---- S = (Q/8) K^T : K frags via ldmatrix (4 x LDSM.x4 per nc) ----
        float s[8][4];
#pragma unroll
        for (int nc = 0; nc < 8; nc++) {
#pragma unroll
            for (int e = 0; e < 4; e++) s[nc][e] = 0.f;
            uint32_t bfr[8][2];
#pragma unroll
            for (int p = 0; p < 4; p++) {
                uint32_t t0, t1, t2, t3;
                LDSM4(t0, t1, t2, t3, kstAddr + (uint32_t)(nc*2176 + p*64) + laneK);
                bfr[2*p][0] = t0;   bfr[2*p][1] = t1;
                bfr[2*p+1][0] = t2; bfr[2*p+1][1] = t3;
            }
#pragma unroll
            for (int kc = 0; kc < 8; kc++)
                MMA_TF32(s[nc], qf[kc], bfr[kc]);
        }

        // ---- online softmax on fragments ----
        float mx0 = -1e30f, mx1 = -1e30f;
#pragma unroll
        for (int nc = 0; nc < 8; nc++) {
            mx0 = fmaxf(mx0, fmaxf(s[nc][0], s[nc][1]));
            mx1 = fmaxf(mx1, fmaxf(s[nc][2], s[nc][3]));
        }
        mx0 = fmaxf(mx0, __shfl_xor_sync(0xffffffffu, mx0, 1));
        mx0 = fmaxf(mx0, __shfl_xor_sync(0xffffffffu, mx0, 2));
        mx1 = fmaxf(mx1, __shfl_xor_sync(0xffffffffu, mx1, 1));
        mx1 = fmaxf(mx1, __shfl_xor_sync(0xffffffffu, mx1, 2));
        float mn0 = fmaxf(m0, mx0), mn1 = fmaxf(m1, mx1);
        float c0 = __expf(m0 - mn0), c1 = __expf(m1 - mn1);
        float sum0 = 0.f, sum1 = 0.f;
#pragma unroll
        for (int nc = 0; nc < 8; nc++) {
            s[nc][0] = __expf(s[nc][0] - mn0); sum0 += s[nc][0];
            s[nc][1] = __expf(s[nc][1] - mn0); sum0 += s[nc][1];
            s[nc][2] = __expf(s[nc][2] - mn1); sum1 += s[nc][2];
            s[nc][3] = __expf(s[nc][3] - mn1); sum1 += s[nc][3];
        }
        sum0 += __shfl_xor_sync(0xffffffffu, sum0, 1);
        sum0 += __shfl_xor_sync(0xffffffffu, sum0, 2);
        sum1 += __shfl_xor_sync(0xffffffffu, sum1, 1);
        sum1 += __shfl_xor_sync(0xffffffffu, sum1, 2);
        l0 = l0*c0 + sum0;  l1 = l1*c1 + sum1;
        m0 = mn0;           m1 = mn1;
#pragma unroll
        for (int nc = 0; nc < 8; nc++) {
            o[nc][0] *= c0; o[nc][1] *= c0;
            o[nc][2] *= c1; o[nc][3] *= c1;
        }

        // ---- P (tf32-rounded) -> smem, warp-private rows ----
#pragma unroll
        for (int nc = 0; nc < 8; nc++) {
            *(float2*)&Pbuf[ r0    *68 + nc*8 + 2*tig] =
                make_float2(__uint_as_float(f2tf32(s[nc][0])),
                            __uint_as_float(f2tf32(s[nc][1])));
            *(float2*)&Pbuf[(r0+8) *68 + nc*8 + 2*tig] =
                make_float2(__uint_as_float(f2tf32(s[nc][2])),
                            __uint_as_float(f2tf32(s[nc][3])));
        }
        __syncwarp();

        // ---- O += P V : P A-frag via ldmatrix, V scalar ----
#pragma unroll
        for (int kc = 0; kc < 8; kc++) {
            uint32_t a[4];
            LDSM4(a[0], a[1], a[2], a[3], pbufAddr + kc*32 + laneP);
#pragma unroll
            for (int nc = 0; nc < 8; nc++) {
                uint32_t bfr[2];
                bfr[0] = __float_as_uint(Vs[(kc*8 + tig    )*72 + nc*8 + g]);
                bfr[1] = __float_as_uint(Vs[(kc*8 + tig + 4)*72 + nc*8 + g]);
                MMA_TF32(o[nc], a, bfr);
            }
        }
        __syncwarp();
    }

    // ---- epilogue: write ctx as bf16 hi/lo pairs ----
    float inv0 = 1.f / l0, inv1 = 1.f / l1;
    size_t base0 = ((size_t)(b*SEQ + q0 + r0    )) * DIM + h*HD;
    size_t base1 = ((size_t)(b*SEQ + q0 + r0 + 8)) * DIM + h*HD;
#pragma unroll
    for (int nc = 0; nc < 8; nc++) {
        float v0 = o[nc][0]*inv0, v1 = o[nc][1]*inv0;
        uint32_t hw = packbf(v0, v1);
        uint32_t lw = packbf(v0 - ubf_lo(hw), v1 - ubf_hi(hw));
        size_t idx = (base0 + nc*8 + 2*tig) >> 1;
        ch[idx] = hw; cl[idx] = lw;
        v0 = o[nc][2]*inv1; v1 = o[nc][3]*inv1;
        hw = packbf(v0, v1);
        lw = packbf(v0 - ubf_lo(hw), v1 - ubf_hi(hw));
        idx = (base1 + nc*8 + 2*tig) >> 1;
        ch[idx] = hw; cl[idx] = lw;
    }
}

// ===========================================================================
extern "C" void kernel_launch(void* const* d_in, const int* in_sizes, int n_in,
                              void* d_out, int out_size)
{
    const float* x  = (const float*)d_in[0];
    const float* wq = (const float*)d_in[1];
    const float* bq = (const float*)d_in[2];
    const float* wk = (const float*)d_in[3];
    const float* bk = (const float*)d_in[4];
    const float* wv = (const float*)d_in[5];
    const float* bv = (const float*)d_in[6];
    const float* wo = (const float*)d_in[7];
    const float* bo = (const float*)d_in[8];

    float *qp, *kp, *vp;
    uint32_t *xh, *xl, *wh, *wl, *ch, *cl;
    cudaGetSymbolAddress((void**)&qp, g_q);
    cudaGetSymbolAddress((void**)&kp, g_k);
    cudaGetSymbolAddress((void**)&vp, g_v);
    cudaGetSymbolAddress((void**)&xh, g_xh);
    cudaGetSymbolAddress((void**)&xl, g_xl);
    cudaGetSymbolAddress((void**)&wh, g_wh);
    cudaGetSymbolAddress((void**)&wl, g_wl);
    cudaGetSymbolAddress((void**)&ch, g_ch);
    cudaGetSymbolAddress((void**)&cl, g_cl);

    cudaFuncSetAttribute(attn_mma,
                         cudaFuncAttributeMaxDynamicSharedMemorySize, ATTN_SMEM);
    cudaFuncSetAttribute(gemm_v2<true>,
                         cudaFuncAttributeMaxDynamicSharedMemorySize, GEMM2_SMEM);
    cudaFuncSetAttribute(gemm_v2<false>,
                         cudaFuncAttributeMaxDynamicSharedMemorySize, GEMM2_SMEM);

    const int WE = DIM*DIM;
    split_k<<<MT*DIM/8/256, 256>>>(x, xh, xl, MT*DIM/8);
    split_w<<<dim3(WE/8/256, 4), 256>>>(wq, wk, wv, wo, wh, wl, WE/8);

    const __nv_bfloat16* xh_b = (const __nv_bfloat16*)xh;
    const __nv_bfloat16* xl_b = (const __nv_bfloat16*)xl;
    const __nv_bfloat16* wh_b = (const __nv_bfloat16*)wh;
    const __nv_bfloat16* wl_b = (const __nv_bfloat16*)wl;
    const __nv_bfloat16* ch_b = (const __nv_bfloat16*)ch;
    const __nv_bfloat16* cl_b = (const __nv_bfloat16*)cl;
    float* out = (float*)d_out;

    gemm_v2<true><<<dim3(DIM/128, MT/128, 3), 128, GEMM2_SMEM>>>(
        xh_b, xl_b, wh_b, wl_b, bq, bk, bv, qp, kp, vp);
    attn_mma<<<dim3(SEQ/64, NH, BB), 128, ATTN_SMEM>>>(qp, kp, vp, ch, cl);
    gemm_v2<false><<<dim3(DIM/128, MT/128, 1), 128, GEMM2_SMEM>>>(
        ch_b, cl_b, wh_b + (size_t)3*WE, wl_b + (size_t)3*WE,
        bo, bo, bo, out, out, out);
}